// round 3
// baseline (speedup 1.0000x reference)
#include <cuda_runtime.h>
#include <cuda_bf16.h>
#include <math.h>

// ---------------- problem constants ----------------
#define BB   8
#define PP   19248
#define MDm  32
#define KK   200
#define PHW  138
#define NPIX (PHW*PHW)
#define HH   512
#define MIDm 64
#define EPSf 1e-6f
#define CONF_T 0.05f
#define NMS_T  0.5f
#define MAXDET 100
#define GS   16

// ---------------- device scratch ----------------
__device__ float g_topv[BB][KK];
__device__ int   g_topi[BB][KK];
__device__ float g_lock[BB][KK][4];     // loc_k
__device__ float g_A[BB][KK][MIDm];     // includes b1
__device__ float g_Bt[BB][MIDm][KK];    // transposed B
__device__ float g_ioT[BB][KK][KK];     // g_ioT[b][j][i] = iou_grid[i][j]
__device__ int   g_cnt[BB];
__device__ float g_keptLoc[BB][KK][4];  // loc_c
__device__ float g_keptConf[BB][KK];    // conf_c
__device__ float g_maskK[BB][KK][MDm];  // mask_c rows (only first cnt valid)
__device__ int   g_idxG[BB][GS];
__device__ int   g_validG[BB][GS];
__device__ float g_final[BB][NPIX];
__device__ double g_var;
__device__ double g_iou;

// ---------------- kernel 0: init accumulators ----------------
__global__ void k_init() { g_var = 0.0; g_iou = 0.0; }

// ---------------- kernel 1: exact top-k via 64-bit radix select ----------------
// composite key = (orderable float bits << 32) | (0xFFFFFFFF - p)
// descending composite order == (value desc, index asc)  -> matches jax.lax.top_k

__device__ __forceinline__ unsigned long long make_comp(const float* conf, int b, int p) {
    float c1 = conf[(b*PP + p)*2 + 1];
    float s = (c1 > CONF_T) ? c1 : -1.0f;
    unsigned u = __float_as_uint(s);
    unsigned k = (u & 0x80000000u) ? ~u : (u | 0x80000000u);
    return ((unsigned long long)k << 32) | (unsigned long long)(0xFFFFFFFFu - (unsigned)p);
}

__global__ void __launch_bounds__(1024) k_topk(const float* __restrict__ conf, const float* __restrict__ loc) {
    __shared__ unsigned long long sel[256];
    __shared__ unsigned int whist[32*256];
    __shared__ unsigned int hsum[256];
    __shared__ unsigned long long s_pref, s_thresh;
    __shared__ int s_need, s_shift, s_done;
    __shared__ unsigned int s_cntsel;

    const int b = blockIdx.x;
    const int tid = threadIdx.x;
    const int nt = blockDim.x;
    const int w = tid >> 5, l = tid & 31;

    if (tid == 0) { s_pref = 0ull; s_need = KK; s_shift = 56; s_done = 0; s_cntsel = 0; }
    if (tid < 256) sel[tid] = 0ull;
    __syncthreads();

    for (int pass = 0; pass < 8; ++pass) {
        __syncthreads();
        if (s_done) break;
        #pragma unroll
        for (int q = 0; q < 8; q++) whist[w*256 + l + q*32] = 0;
        __syncthreads();
        unsigned long long pref = s_pref;
        int shift = s_shift;
        unsigned long long maskHigh = (shift >= 56) ? 0ull : (~0ull << (shift + 8));
        for (int p = tid; p < PP; p += nt) {
            unsigned long long comp = make_comp(conf, b, p);
            if ((comp & maskHigh) == pref)
                atomicAdd(&whist[w*256 + (unsigned)((comp >> shift) & 255u)], 1u);
        }
        __syncthreads();
        if (tid < 256) {
            unsigned s = 0;
            #pragma unroll 8
            for (int ww = 0; ww < 32; ww++) s += whist[ww*256 + tid];
            hsum[tid] = s;
        }
        __syncthreads();
        if (tid == 0) {
            int need = s_need;
            unsigned acc = 0;
            int bin = 255;
            for (; bin >= 0; --bin) {
                unsigned c = hsum[bin];
                if (acc + c >= (unsigned)need) break;
                acc += c;
            }
            if (bin < 0) bin = 0; // safety (cannot happen)
            unsigned long long np = s_pref | ((unsigned long long)(unsigned)bin << s_shift);
            int nin = need - (int)acc;
            if ((unsigned)nin == hsum[bin] || s_shift == 0) {
                s_done = 1;
                s_thresh = np;
            } else {
                s_pref = np;
                s_need = nin;
                s_shift = s_shift - 8;
            }
        }
    }
    __syncthreads();
    unsigned long long thr = s_thresh;
    for (int p = tid; p < PP; p += nt) {
        unsigned long long comp = make_comp(conf, b, p);
        if (comp >= thr) {
            unsigned pos = atomicAdd(&s_cntsel, 1u);
            if (pos < 256) sel[pos] = comp;
        }
    }
    __syncthreads();
    // bitonic sort ascending, 256 elements
    for (int k = 2; k <= 256; k <<= 1) {
        for (int j = k >> 1; j > 0; j >>= 1) {
            if (tid < 256) {
                int ixj = tid ^ j;
                if (ixj > tid) {
                    unsigned long long a = sel[tid], c = sel[ixj];
                    bool up = ((tid & k) == 0);
                    if ((a > c) == up) { sel[tid] = c; sel[ixj] = a; }
                }
            }
            __syncthreads();
        }
    }
    if (tid < KK) {
        unsigned long long comp = sel[255 - tid];
        int p = (int)(0xFFFFFFFFu - (unsigned)(comp & 0xFFFFFFFFull));
        float c1 = conf[(b*PP + p)*2 + 1];
        float s = (c1 > CONF_T) ? c1 : -1.0f;
        g_topv[b][tid] = s;
        g_topi[b][tid] = p;
        #pragma unroll
        for (int d = 0; d < 4; d++) g_lock[b][tid][d] = loc[(b*PP + p)*4 + d];
    }
}

// ---------------- kernel 2: A (with b1) and B^T ----------------
__global__ void k_ab(const float* __restrict__ W1, const float* __restrict__ b1) {
    int b = blockIdx.x;
    for (int idx = threadIdx.x; idx < KK*MIDm; idx += blockDim.x) {
        int j = idx >> 6, m = idx & 63;
        const float* lk = &g_lock[b][j][0];
        float a = b1[m], bt = 0.f;
        #pragma unroll
        for (int d = 0; d < 4; d++) {
            a  = fmaf(lk[d], W1[d*MIDm + m],       a);
            bt = fmaf(lk[d], W1[(4+d)*MIDm + m],   bt);
        }
        g_A[b][j][m] = a;
        g_Bt[b][m][j] = bt;
    }
}

// ---------------- kernel 3: iou grid (transposed store) ----------------
__global__ void k_iougrid(const float* __restrict__ W2, const float* __restrict__ b2) {
    int j = blockIdx.x, b = blockIdx.y;
    __shared__ float a_s[MIDm], w2_s[MIDm];
    __shared__ float b2s;
    int tid = threadIdx.x;
    if (tid < MIDm) { a_s[tid] = g_A[b][j][tid]; w2_s[tid] = W2[tid]; }
    if (tid == 0) b2s = b2[0];
    __syncthreads();
    if (tid < KK) {
        float logit = b2s;
        #pragma unroll 8
        for (int m = 0; m < MIDm; m++) {
            float h = a_s[m] + g_Bt[b][m][tid];
            h = fmaxf(h, 0.f);
            logit = fmaf(h, w2_s[m], logit);
        }
        g_ioT[b][j][tid] = 1.0f / (1.0f + expf(-logit));   // accurate exp: NMS boundary decision
    }
}

// ---------------- kernel 4: NMS, cumsum clamp, stable partition, compaction ----------------
__global__ void k_nms(const float* __restrict__ mask) {
    int b = blockIdx.x, tid = threadIdx.x;
    __shared__ unsigned char valid_s[KK];
    __shared__ unsigned char keep_s[KK];
    __shared__ short perm_s[KK];
    __shared__ int cnt_s;
    if (tid < KK) valid_s[tid] = (g_topv[b][tid] > CONF_T) ? 1 : 0;
    __syncthreads();
    if (tid < KK) {
        int j = tid;
        float mx = 0.f;
        const float* row = &g_ioT[b][j][0];
        for (int i = 0; i < j; i++)
            if (valid_s[i]) mx = fmaxf(mx, row[i]);
        keep_s[j] = ((mx <= NMS_T) && valid_s[j]) ? 1 : 0;
    }
    __syncthreads();
    if (tid == 0) {
        int run = 0;
        for (int j = 0; j < KK; j++) {
            if (keep_s[j]) { run++; if (run > MAXDET) keep_s[j] = 0; }
        }
        int pos = 0;
        for (int j = 0; j < KK; j++) if (keep_s[j])  perm_s[pos++] = (short)j;
        cnt_s = pos;
        for (int j = 0; j < KK; j++) if (!keep_s[j]) perm_s[pos++] = (short)j;
        g_cnt[b] = cnt_s;
    }
    __syncthreads();
    int cnt = cnt_s;
    if (tid < KK) {
        int pj = perm_s[tid];
        bool kept = tid < cnt;
        g_keptConf[b][tid] = kept ? g_topv[b][pj] : 0.f;
        #pragma unroll
        for (int d = 0; d < 4; d++) g_keptLoc[b][tid][d] = g_lock[b][pj][d];
    }
    if (tid < GS) {
        g_idxG[b][tid] = perm_s[tid];
        g_validG[b][tid] = (tid < cnt) ? 1 : 0;
    }
    __syncthreads();
    for (int t = tid; t < cnt*MDm; t += blockDim.x) {
        int k = t >> 5, c = t & 31;
        g_maskK[b][k][c] = mask[(b*PP + g_topi[b][perm_s[k]])*MDm + c];
    }
}

// ---------------- kernel 5: IOU training loss ----------------
__global__ void k_iouloss() {
    int b = blockIdx.y;
    int pr = blockIdx.x;
    int a = pr >> 4, c = pr & 15;
    if (!(g_validG[b][a] && g_validG[b][c])) return;
    __shared__ float gy0[64], gx0[64], gy1[64], gx1[64];
    __shared__ float s_i[2], s_u[2];
    int t = threadIdx.x;  // 64 threads
    const float* la = &g_keptLoc[b][a][0];
    const float* lb = &g_keptLoc[b][c][0];
    float coord = (t + 0.5f) / 64.0f;
    {
        float d0 = (coord - la[1]) / (la[3]*0.5f + EPSf); gy0[t] = expf(-0.5f*d0*d0);
        float d1 = (coord - la[0]) / (la[2]*0.5f + EPSf); gx0[t] = expf(-0.5f*d1*d1);
        float d2 = (coord - lb[1]) / (lb[3]*0.5f + EPSf); gy1[t] = expf(-0.5f*d2*d2);
        float d3 = (coord - lb[0]) / (lb[2]*0.5f + EPSf); gx1[t] = expf(-0.5f*d3*d3);
    }
    __syncthreads();
    float inter = 0.f, uni = 0.f;
    float ya = gy0[t], yb = gy1[t];
    #pragma unroll 4
    for (int x = 0; x < 64; x++) {
        float va = ya * gx0[x];
        float vb = yb * gx1[x];
        inter += fminf(va, vb);
        uni   += fmaxf(va, vb);
    }
    #pragma unroll
    for (int o = 16; o > 0; o >>= 1) {
        inter += __shfl_down_sync(0xffffffffu, inter, o);
        uni   += __shfl_down_sync(0xffffffffu, uni, o);
    }
    if ((t & 31) == 0) { s_i[t >> 5] = inter; s_u[t >> 5] = uni; }
    __syncthreads();
    if (t == 0) {
        float I = s_i[0] + s_i[1], U = s_u[0] + s_u[1];
        float giou = I / (U + EPSf);
        float pred = g_ioT[b][g_idxG[b][c]][g_idxG[b][a]];
        float d = pred - giou;
        atomicAdd(&g_iou, (double)(d * d));
    }
}

// ---------------- kernel 6: fused final map ----------------
__global__ void k_final(const float* __restrict__ proto) {
    int b = blockIdx.y, tid = threadIdx.x;
    __shared__ __align__(16) float smask[MAXDET*MDm];
    __shared__ float sconf[MAXDET], scx[MAXDET], scy[MAXDET], sibw[MAXDET], sibh[MAXDET];
    int cnt = g_cnt[b];
    for (int t = tid; t < cnt*MDm; t += blockDim.x) smask[t] = (&g_maskK[b][0][0])[t];
    for (int t = tid; t < cnt; t += blockDim.x) {
        sconf[t] = g_keptConf[b][t];
        scx[t] = g_keptLoc[b][t][0];
        scy[t] = g_keptLoc[b][t][1];
        sibw[t] = 1.0f / (g_keptLoc[b][t][2]*0.5f + EPSf);
        sibh[t] = 1.0f / (g_keptLoc[b][t][3]*0.5f + EPSf);
    }
    __syncthreads();
    int pix = blockIdx.x * blockDim.x + tid;
    if (pix >= NPIX) return;
    int h = pix / PHW, w = pix - h*PHW;
    float yc = (h + 0.5f) / (float)PHW;
    float xc = (w + 0.5f) / (float)PHW;
    const float4* pr4 = (const float4*)&proto[((long long)(b*NPIX + pix)) * MDm];
    float pv[32];
    #pragma unroll
    for (int q = 0; q < 8; q++) {
        float4 t4 = pr4[q];
        pv[4*q] = t4.x; pv[4*q+1] = t4.y; pv[4*q+2] = t4.z; pv[4*q+3] = t4.w;
    }
    float s1 = 0.f, s2 = 0.f;
    for (int k = 0; k < cnt; k++) {
        const float4* m4 = (const float4*)(smask + k*MDm);
        float dot = 0.f;
        #pragma unroll
        for (int q = 0; q < 8; q++) {
            float4 mm = m4[q];
            dot = fmaf(pv[4*q],   mm.x, dot);
            dot = fmaf(pv[4*q+1], mm.y, dot);
            dot = fmaf(pv[4*q+2], mm.z, dot);
            dot = fmaf(pv[4*q+3], mm.w, dot);
        }
        float sig = 1.0f / (1.0f + __expf(-dot));
        float ty = (yc - scy[k]) * sibh[k];
        float tx = (xc - scx[k]) * sibw[k];
        float g = __expf(-0.5f * (ty*ty + tx*tx));
        float m = sig * g * sconf[k];
        s1 += m;
        s2 = fmaf(m, m, s2);
    }
    g_final[b][pix] = 1.0f - s2 / (s1 + EPSf);
}

// ---------------- kernel 7: fused bilinear resize + weighted variance ----------------
__global__ void k_var(const float* __restrict__ orig) {
    int pix = blockIdx.x * blockDim.x + threadIdx.x;
    double v = 0.0;
    if (pix < HH*HH) {
        int h = pix >> 9, w = pix & 511;
        const float SC = (float)PHW / (float)HH;
        float py = (h + 0.5f) * SC - 0.5f;
        float px = (w + 0.5f) * SC - 0.5f;
        float fy0 = floorf(py), fx0 = floorf(px);
        float fy = py - fy0, fx = px - fx0;
        int y0 = (int)fy0, x0 = (int)fx0;
        int iy0 = min(PHW-1, max(0, y0));
        int iy1 = min(PHW-1, max(0, y0+1));
        int ix0 = min(PHW-1, max(0, x0));
        int ix1 = min(PHW-1, max(0, x0+1));
        float r[BB];
        float tot = 0.f;
        #pragma unroll
        for (int b = 0; b < BB; b++) {
            const float* f = g_final[b];
            float v00 = f[iy0*PHW + ix0], v01 = f[iy0*PHW + ix1];
            float v10 = f[iy1*PHW + ix0], v11 = f[iy1*PHW + ix1];
            float top = v00 + (v01 - v00) * fx;
            float bot = v10 + (v11 - v10) * fx;
            float rv = top + (bot - top) * fy;
            r[b] = rv;
            tot += rv;
        }
        float acc = 0.f;
        #pragma unroll
        for (int c = 0; c < 3; c++) {
            float o[BB];
            float wm = 0.f;
            #pragma unroll
            for (int b = 0; b < BB; b++) {
                o[b] = orig[((b*3 + c)*HH + h)*HH + w];
                wm = fmaf(o[b], r[b], wm);
            }
            #pragma unroll
            for (int b = 0; b < BB; b++) {
                float d = o[b] - wm;
                acc = fmaf(d*d, r[b], acc);
            }
        }
        v = (double)(acc / (tot + EPSf));
    }
    #pragma unroll
    for (int o = 16; o > 0; o >>= 1) v += __shfl_down_sync(0xffffffffu, v, o);
    __shared__ double sd[8];
    int lane = threadIdx.x & 31, wid = threadIdx.x >> 5;
    if (lane == 0) sd[wid] = v;
    __syncthreads();
    if (wid == 0) {
        double x = (lane < (int)(blockDim.x >> 5)) ? sd[lane] : 0.0;
        #pragma unroll
        for (int o = 4; o > 0; o >>= 1) x += __shfl_down_sync(0xffffffffu, x, o);
        if (lane == 0) atomicAdd(&g_var, x);
    }
}

// ---------------- kernel 8: write output ----------------
__global__ void k_write(float* __restrict__ out) {
    out[0] = (float)g_var;
    out[1] = (float)g_iou;
}

// ---------------- launch ----------------
extern "C" void kernel_launch(void* const* d_in, const int* in_sizes, int n_in,
                              void* d_out, int out_size) {
    const float* original = (const float*)d_in[0];
    const float* loc      = (const float*)d_in[1];
    const float* conf     = (const float*)d_in[2];
    const float* mask     = (const float*)d_in[3];
    const float* proto    = (const float*)d_in[4];
    const float* W1       = (const float*)d_in[5];
    const float* b1       = (const float*)d_in[6];
    const float* W2       = (const float*)d_in[7];
    const float* b2       = (const float*)d_in[8];
    float* out            = (float*)d_out;

    k_init<<<1, 1>>>();
    k_topk<<<BB, 1024>>>(conf, loc);
    k_ab<<<BB, 256>>>(W1, b1);
    k_iougrid<<<dim3(KK, BB), 256>>>(W2, b2);
    k_nms<<<BB, 256>>>(mask);
    k_iouloss<<<dim3(GS*GS, BB), 64>>>();
    k_final<<<dim3((NPIX + 127) / 128, BB), 128>>>(proto);
    k_var<<<(HH*HH + 255) / 256, 256>>>(original);
    k_write<<<1, 1>>>(out);
}

// round 4
// speedup vs baseline: 1.1922x; 1.1922x over previous
#include <cuda_runtime.h>
#include <cuda_bf16.h>
#include <math.h>

// ---------------- problem constants ----------------
#define BB   8
#define PP   19248
#define MDm  32
#define KK   200
#define PHW  138
#define NPIX (PHW*PHW)
#define HH   512
#define MIDm 64
#define EPSf 1e-6f
#define CONF_T 0.05f
#define NMS_T  0.5f
#define MAXDET 100
#define GS   16
#define JT   8      // j-rows per block in k_iougrid

// ---------------- device scratch ----------------
__device__ float g_topv[BB][KK];
__device__ int   g_topi[BB][KK];
__device__ float g_lock[BB][KK][4];     // loc_k
__device__ float g_A[BB][KK][MIDm];     // includes b1
__device__ float g_Bt[BB][MIDm][KK];    // transposed B
__device__ float g_ioT[BB][KK][KK];     // g_ioT[b][j][i] = iou_grid[i][j]
__device__ int   g_cnt[BB];
__device__ float g_keptLoc[BB][KK][4];  // loc_c
__device__ float g_keptConf[BB][KK];    // conf_c
__device__ float g_maskK[BB][KK][MDm];  // mask_c rows (only first cnt valid)
__device__ int   g_idxG[BB][GS];
__device__ int   g_validG[BB][GS];
__device__ float g_final[BB][NPIX];
__device__ double g_var;
__device__ double g_iou;

// ---------------- kernel 1: top-k (radix select on smem-staged keys) + A/Bt + init ----------------
// composite key = (orderable float bits << 32) | (0xFFFFFFFF - p)
// descending composite order == (value desc, index asc)  -> matches jax.lax.top_k

__global__ void __launch_bounds__(1024) k_topk(const float* __restrict__ conf,
                                               const float* __restrict__ loc,
                                               const float* __restrict__ W1,
                                               const float* __restrict__ b1) {
    extern __shared__ unsigned skey[];             // PP keys (77 KB dynamic)
    __shared__ unsigned long long sel[256];
    __shared__ unsigned int whist[32*256];
    __shared__ unsigned int hsum[256];
    __shared__ float sloc[KK][4];
    __shared__ unsigned long long s_pref, s_thresh;
    __shared__ int s_need, s_shift, s_done;
    __shared__ unsigned int s_cntsel;

    const int b = blockIdx.x;
    const int tid = threadIdx.x;
    const int nt = blockDim.x;
    const int w = tid >> 5, l = tid & 31;

    // init global accumulators once
    if (b == 0 && tid == 0) { g_var = 0.0; g_iou = 0.0; }

    // stage keys in smem (coalesced float2 loads: .y is conf[:,:,1])
    const float2* c2 = (const float2*)conf + (size_t)b * PP;
    for (int p = tid; p < PP; p += nt) {
        float c1 = c2[p].y;
        float s = (c1 > CONF_T) ? c1 : -1.0f;
        unsigned u = __float_as_uint(s);
        skey[p] = (u & 0x80000000u) ? ~u : (u | 0x80000000u);
    }
    if (tid == 0) { s_pref = 0ull; s_need = KK; s_shift = 56; s_done = 0; s_cntsel = 0; }
    if (tid < 256) sel[tid] = 0ull;
    __syncthreads();

    for (int pass = 0; pass < 8; ++pass) {
        __syncthreads();
        if (s_done) break;
        #pragma unroll
        for (int q = 0; q < 8; q++) whist[w*256 + l + q*32] = 0;
        __syncthreads();
        unsigned long long pref = s_pref;
        int shift = s_shift;
        unsigned long long maskHigh = (shift >= 56) ? 0ull : (~0ull << (shift + 8));
        for (int p = tid; p < PP; p += nt) {
            unsigned long long comp = ((unsigned long long)skey[p] << 32) | (unsigned long long)(0xFFFFFFFFu - (unsigned)p);
            if ((comp & maskHigh) == pref)
                atomicAdd(&whist[w*256 + (unsigned)((comp >> shift) & 255u)], 1u);
        }
        __syncthreads();
        if (tid < 256) {
            unsigned s = 0;
            #pragma unroll 8
            for (int ww = 0; ww < 32; ww++) s += whist[ww*256 + tid];
            hsum[tid] = s;
        }
        __syncthreads();
        if (tid == 0) {
            int need = s_need;
            unsigned acc = 0;
            int bin = 255;
            for (; bin >= 0; --bin) {
                unsigned c = hsum[bin];
                if (acc + c >= (unsigned)need) break;
                acc += c;
            }
            if (bin < 0) bin = 0; // safety (cannot happen)
            unsigned long long np = s_pref | ((unsigned long long)(unsigned)bin << s_shift);
            int nin = need - (int)acc;
            if ((unsigned)nin == hsum[bin] || s_shift == 0) {
                s_done = 1;
                s_thresh = np;
            } else {
                s_pref = np;
                s_need = nin;
                s_shift = s_shift - 8;
            }
        }
    }
    __syncthreads();
    unsigned long long thr = s_thresh;
    for (int p = tid; p < PP; p += nt) {
        unsigned long long comp = ((unsigned long long)skey[p] << 32) | (unsigned long long)(0xFFFFFFFFu - (unsigned)p);
        if (comp >= thr) {
            unsigned pos = atomicAdd(&s_cntsel, 1u);
            if (pos < 256) sel[pos] = comp;
        }
    }
    __syncthreads();
    // bitonic sort ascending, 256 elements
    for (int k = 2; k <= 256; k <<= 1) {
        for (int j = k >> 1; j > 0; j >>= 1) {
            if (tid < 256) {
                int ixj = tid ^ j;
                if (ixj > tid) {
                    unsigned long long a = sel[tid], c = sel[ixj];
                    bool up = ((tid & k) == 0);
                    if ((a > c) == up) { sel[tid] = c; sel[ixj] = a; }
                }
            }
            __syncthreads();
        }
    }
    if (tid < KK) {
        unsigned long long comp = sel[255 - tid];
        int p = (int)(0xFFFFFFFFu - (unsigned)(comp & 0xFFFFFFFFull));
        unsigned k = (unsigned)(comp >> 32);
        // invert orderable-key transform to recover the score
        float s = (k & 0x80000000u) ? __uint_as_float(k & 0x7FFFFFFFu) : __uint_as_float(~k);
        g_topv[b][tid] = s;
        g_topi[b][tid] = p;
        const float4 lv = *(const float4*)&loc[((size_t)b*PP + p)*4];
        g_lock[b][tid][0] = lv.x; g_lock[b][tid][1] = lv.y;
        g_lock[b][tid][2] = lv.z; g_lock[b][tid][3] = lv.w;
        sloc[tid][0] = lv.x; sloc[tid][1] = lv.y; sloc[tid][2] = lv.z; sloc[tid][3] = lv.w;
    }
    __syncthreads();
    // fused A (with b1) and B^T
    for (int idx = tid; idx < KK*MIDm; idx += nt) {
        int j = idx >> 6, m = idx & 63;
        float a = b1[m], bt = 0.f;
        #pragma unroll
        for (int d = 0; d < 4; d++) {
            float ld = sloc[j][d];
            a  = fmaf(ld, W1[d*MIDm + m],     a);
            bt = fmaf(ld, W1[(4+d)*MIDm + m], bt);
        }
        g_A[b][j][m] = a;
        g_Bt[b][m][j] = bt;
    }
}

// ---------------- kernel 3: iou grid, JT rows per block (transposed store) ----------------
__global__ void __launch_bounds__(256) k_iougrid(const float* __restrict__ W2, const float* __restrict__ b2) {
    int b = blockIdx.y, j0 = blockIdx.x * JT;
    __shared__ float a_s[JT][MIDm];
    __shared__ float w2_s[MIDm];
    __shared__ float b2s;
    int t = threadIdx.x;
    for (int idx = t; idx < JT*MIDm; idx += 256) {
        int jj = idx >> 6, m = idx & 63;
        a_s[jj][m] = g_A[b][j0 + jj][m];
    }
    if (t < MIDm) w2_s[t] = W2[t];
    if (t == 0) b2s = b2[0];
    __syncthreads();
    if (t < KK) {
        float logit[JT];
        #pragma unroll
        for (int jj = 0; jj < JT; jj++) logit[jj] = b2s;
        #pragma unroll 4
        for (int m = 0; m < MIDm; m++) {
            float bt = g_Bt[b][m][t];
            float w2 = w2_s[m];
            #pragma unroll
            for (int jj = 0; jj < JT; jj++) {
                float h = fmaxf(a_s[jj][m] + bt, 0.f);
                logit[jj] = fmaf(h, w2, logit[jj]);
            }
        }
        #pragma unroll
        for (int jj = 0; jj < JT; jj++)
            g_ioT[b][j0 + jj][t] = 1.0f / (1.0f + expf(-logit[jj]));  // accurate exp: NMS boundary
    }
}

// ---------------- kernel 4: NMS, cumsum clamp, stable partition, compaction ----------------
__global__ void __launch_bounds__(256) k_nms(const float* __restrict__ mask) {
    int b = blockIdx.x, tid = threadIdx.x;
    __shared__ float vmask_s[KK];      // 1.0 if valid else 0.0
    __shared__ unsigned char keep_s[KK];
    __shared__ short perm_s[KK];
    __shared__ int cnt_s;
    if (tid < KK) vmask_s[tid] = (g_topv[b][tid] > CONF_T) ? 1.0f : 0.0f;
    __syncthreads();
    if (tid < KK) {
        int j = tid;
        float mx = 0.f;
        const float4* row4 = (const float4*)&g_ioT[b][j][0];   // row is 800B, 16B-aligned
        int full = j >> 2;
        for (int q = 0; q < full; q++) {
            float4 v = row4[q];
            const float* vm = &vmask_s[q*4];
            mx = fmaxf(mx, v.x * vm[0]);
            mx = fmaxf(mx, v.y * vm[1]);
            mx = fmaxf(mx, v.z * vm[2]);
            mx = fmaxf(mx, v.w * vm[3]);
        }
        for (int i = full*4; i < j; i++)
            mx = fmaxf(mx, g_ioT[b][j][i] * vmask_s[i]);
        keep_s[j] = ((mx <= NMS_T) && (vmask_s[j] > 0.f)) ? 1 : 0;
    }
    __syncthreads();
    if (tid == 0) {
        int run = 0;
        for (int j = 0; j < KK; j++) {
            if (keep_s[j]) { run++; if (run > MAXDET) keep_s[j] = 0; }
        }
        int pos = 0;
        for (int j = 0; j < KK; j++) if (keep_s[j])  perm_s[pos++] = (short)j;
        cnt_s = pos;
        for (int j = 0; j < KK; j++) if (!keep_s[j]) perm_s[pos++] = (short)j;
        g_cnt[b] = cnt_s;
    }
    __syncthreads();
    int cnt = cnt_s;
    if (tid < KK) {
        int pj = perm_s[tid];
        bool kept = tid < cnt;
        g_keptConf[b][tid] = kept ? g_topv[b][pj] : 0.f;
        #pragma unroll
        for (int d = 0; d < 4; d++) g_keptLoc[b][tid][d] = g_lock[b][pj][d];
    }
    if (tid < GS) {
        g_idxG[b][tid] = perm_s[tid];
        g_validG[b][tid] = (tid < cnt) ? 1 : 0;
    }
    __syncthreads();
    for (int t = tid; t < cnt*MDm; t += blockDim.x) {
        int k = t >> 5, c = t & 31;
        g_maskK[b][k][c] = mask[((size_t)b*PP + g_topi[b][perm_s[k]])*MDm + c];
    }
}

// ---------------- kernel 5: IOU training loss ----------------
__global__ void k_iouloss() {
    int b = blockIdx.y;
    int pr = blockIdx.x;
    int a = pr >> 4, c = pr & 15;
    if (!(g_validG[b][a] && g_validG[b][c])) return;
    __shared__ float gy0[64], gx0[64], gy1[64], gx1[64];
    __shared__ float s_i[2], s_u[2];
    int t = threadIdx.x;  // 64 threads
    const float* la = &g_keptLoc[b][a][0];
    const float* lb = &g_keptLoc[b][c][0];
    float coord = (t + 0.5f) / 64.0f;
    {
        float d0 = (coord - la[1]) / (la[3]*0.5f + EPSf); gy0[t] = expf(-0.5f*d0*d0);
        float d1 = (coord - la[0]) / (la[2]*0.5f + EPSf); gx0[t] = expf(-0.5f*d1*d1);
        float d2 = (coord - lb[1]) / (lb[3]*0.5f + EPSf); gy1[t] = expf(-0.5f*d2*d2);
        float d3 = (coord - lb[0]) / (lb[2]*0.5f + EPSf); gx1[t] = expf(-0.5f*d3*d3);
    }
    __syncthreads();
    float inter = 0.f, uni = 0.f;
    float ya = gy0[t], yb = gy1[t];
    #pragma unroll 4
    for (int x = 0; x < 64; x++) {
        float va = ya * gx0[x];
        float vb = yb * gx1[x];
        inter += fminf(va, vb);
        uni   += fmaxf(va, vb);
    }
    #pragma unroll
    for (int o = 16; o > 0; o >>= 1) {
        inter += __shfl_down_sync(0xffffffffu, inter, o);
        uni   += __shfl_down_sync(0xffffffffu, uni, o);
    }
    if ((t & 31) == 0) { s_i[t >> 5] = inter; s_u[t >> 5] = uni; }
    __syncthreads();
    if (t == 0) {
        float I = s_i[0] + s_i[1], U = s_u[0] + s_u[1];
        float giou = I / (U + EPSf);
        float pred = g_ioT[b][g_idxG[b][c]][g_idxG[b][a]];
        float d = pred - giou;
        atomicAdd(&g_iou, (double)(d * d));
    }
}

// ---------------- kernel 6: fused final map ----------------
__global__ void __launch_bounds__(128) k_final(const float* __restrict__ proto) {
    int b = blockIdx.y, tid = threadIdx.x;
    __shared__ __align__(16) float smask[MAXDET*MDm];
    __shared__ float sconf[MAXDET], scx[MAXDET], scy[MAXDET], sibw[MAXDET], sibh[MAXDET];
    int cnt = g_cnt[b];
    for (int t = tid; t < cnt*MDm; t += blockDim.x) smask[t] = (&g_maskK[b][0][0])[t];
    for (int t = tid; t < cnt; t += blockDim.x) {
        sconf[t] = g_keptConf[b][t];
        scx[t] = g_keptLoc[b][t][0];
        scy[t] = g_keptLoc[b][t][1];
        sibw[t] = 1.0f / (g_keptLoc[b][t][2]*0.5f + EPSf);
        sibh[t] = 1.0f / (g_keptLoc[b][t][3]*0.5f + EPSf);
    }
    __syncthreads();
    int pix = blockIdx.x * blockDim.x + tid;
    if (pix >= NPIX) return;
    int h = pix / PHW, w = pix - h*PHW;
    float yc = (h + 0.5f) / (float)PHW;
    float xc = (w + 0.5f) / (float)PHW;
    const float4* pr4 = (const float4*)&proto[((size_t)(b*NPIX + pix)) * MDm];
    float pv[32];
    #pragma unroll
    for (int q = 0; q < 8; q++) {
        float4 t4 = pr4[q];
        pv[4*q] = t4.x; pv[4*q+1] = t4.y; pv[4*q+2] = t4.z; pv[4*q+3] = t4.w;
    }
    float s1 = 0.f, s2 = 0.f;
    for (int k = 0; k < cnt; k++) {
        const float4* m4 = (const float4*)(smask + k*MDm);
        float dot = 0.f;
        #pragma unroll
        for (int q = 0; q < 8; q++) {
            float4 mm = m4[q];
            dot = fmaf(pv[4*q],   mm.x, dot);
            dot = fmaf(pv[4*q+1], mm.y, dot);
            dot = fmaf(pv[4*q+2], mm.z, dot);
            dot = fmaf(pv[4*q+3], mm.w, dot);
        }
        float sig = 1.0f / (1.0f + __expf(-dot));
        float ty = (yc - scy[k]) * sibh[k];
        float tx = (xc - scx[k]) * sibw[k];
        float g = __expf(-0.5f * (ty*ty + tx*tx));
        float m = sig * g * sconf[k];
        s1 += m;
        s2 = fmaf(m, m, s2);
    }
    g_final[b][pix] = 1.0f - s2 / (s1 + EPSf);
}

// ---------------- kernel 7: fused bilinear resize + weighted variance ----------------
__global__ void __launch_bounds__(256) k_var(const float* __restrict__ orig) {
    int pix = blockIdx.x * blockDim.x + threadIdx.x;
    double v = 0.0;
    if (pix < HH*HH) {
        int h = pix >> 9, w = pix & 511;
        const float SC = (float)PHW / (float)HH;
        float py = (h + 0.5f) * SC - 0.5f;
        float px = (w + 0.5f) * SC - 0.5f;
        float fy0 = floorf(py), fx0 = floorf(px);
        float fy = py - fy0, fx = px - fx0;
        int y0 = (int)fy0, x0 = (int)fx0;
        int iy0 = min(PHW-1, max(0, y0));
        int iy1 = min(PHW-1, max(0, y0+1));
        int ix0 = min(PHW-1, max(0, x0));
        int ix1 = min(PHW-1, max(0, x0+1));
        float r[BB];
        float tot = 0.f;
        #pragma unroll
        for (int b = 0; b < BB; b++) {
            const float* f = g_final[b];
            float v00 = f[iy0*PHW + ix0], v01 = f[iy0*PHW + ix1];
            float v10 = f[iy1*PHW + ix0], v11 = f[iy1*PHW + ix1];
            float top = v00 + (v01 - v00) * fx;
            float bot = v10 + (v11 - v10) * fx;
            float rv = top + (bot - top) * fy;
            r[b] = rv;
            tot += rv;
        }
        float acc = 0.f;
        #pragma unroll
        for (int c = 0; c < 3; c++) {
            float o[BB];
            float wm = 0.f;
            #pragma unroll
            for (int b = 0; b < BB; b++) {
                o[b] = orig[((b*3 + c)*HH + h)*HH + w];
                wm = fmaf(o[b], r[b], wm);
            }
            #pragma unroll
            for (int b = 0; b < BB; b++) {
                float d = o[b] - wm;
                acc = fmaf(d*d, r[b], acc);
            }
        }
        v = (double)(acc / (tot + EPSf));
    }
    #pragma unroll
    for (int o = 16; o > 0; o >>= 1) v += __shfl_down_sync(0xffffffffu, v, o);
    __shared__ double sd[8];
    int lane = threadIdx.x & 31, wid = threadIdx.x >> 5;
    if (lane == 0) sd[wid] = v;
    __syncthreads();
    if (wid == 0) {
        double x = (lane < (int)(blockDim.x >> 5)) ? sd[lane] : 0.0;
        #pragma unroll
        for (int o = 4; o > 0; o >>= 1) x += __shfl_down_sync(0xffffffffu, x, o);
        if (lane == 0) atomicAdd(&g_var, x);
    }
}

// ---------------- kernel 8: write output ----------------
__global__ void k_write(float* __restrict__ out) {
    out[0] = (float)g_var;
    out[1] = (float)g_iou;
}

// ---------------- launch ----------------
extern "C" void kernel_launch(void* const* d_in, const int* in_sizes, int n_in,
                              void* d_out, int out_size) {
    const float* original = (const float*)d_in[0];
    const float* loc      = (const float*)d_in[1];
    const float* conf     = (const float*)d_in[2];
    const float* mask     = (const float*)d_in[3];
    const float* proto    = (const float*)d_in[4];
    const float* W1       = (const float*)d_in[5];
    const float* b1       = (const float*)d_in[6];
    const float* W2       = (const float*)d_in[7];
    const float* b2       = (const float*)d_in[8];
    float* out            = (float*)d_out;

    const int smem_topk = PP * 4;   // 76992 bytes dynamic
    cudaFuncSetAttribute(k_topk, cudaFuncAttributeMaxDynamicSharedMemorySize, smem_topk);

    k_topk<<<BB, 1024, smem_topk>>>(conf, loc, W1, b1);
    k_iougrid<<<dim3(KK/JT, BB), 256>>>(W2, b2);
    k_nms<<<BB, 256>>>(mask);
    k_iouloss<<<dim3(GS*GS, BB), 64>>>();
    k_final<<<dim3((NPIX + 127) / 128, BB), 128>>>(proto);
    k_var<<<(HH*HH + 255) / 256, 256>>>(original);
    k_write<<<1, 1>>>(out);
}